// round 13
// baseline (speedup 1.0000x reference)
#include <cuda_runtime.h>
#include <cstdint>

// Problem constants
#define BATCH 8
#define NN    4096
#define CC    64
#define KOUT  8            // neighbors kept (self excluded explicitly)
#define TI 64
#define TJ 64
#define PADJ 68            // Xj / dt row stride (floats): scan conflict-free, 16B rows
#define PADI 132           // duplicated Xi row stride (floats): 16B rows, 4-way STS
#define THREADS 256

#define NODES_ELEMS (BATCH * NN * CC)
#define EDGE_PER_B  (2 * NN * KOUT)

// smem partition (floats)
#define F_XI2  (CC * PADI)          // 8448
#define F_XJ   (CC * PADJ)          // 4352 (aliased as dt)
#define SMEM_FLOATS (F_XI2 + F_XJ + 128 + 64)
#define SMEM_BYTES  (SMEM_FLOATS * 4)   // 51,968 B

__device__ float g_xx[BATCH * NN];

// ---- f32x2 packed helpers (sm_100-family PTX, not 'a'-gated) ----
__device__ __forceinline__ void ffma2(unsigned long long& d,
                                      unsigned long long a, unsigned long long b) {
    asm("fma.rn.f32x2 %0, %1, %2, %0;" : "+l"(d) : "l"(a), "l"(b));
}
__device__ __forceinline__ unsigned long long fma2v(unsigned long long a,
                                                    unsigned long long b,
                                                    unsigned long long c) {
    unsigned long long d;
    asm("fma.rn.f32x2 %0, %1, %2, %3;" : "=l"(d) : "l"(a), "l"(b), "l"(c));
    return d;
}
__device__ __forceinline__ unsigned long long add2v(unsigned long long a,
                                                    unsigned long long b) {
    unsigned long long d;
    asm("add.rn.f32x2 %0, %1, %2;" : "=l"(d) : "l"(a), "l"(b));
    return d;
}

// ---------------------------------------------------------------------------
// Kernel A: projection + squared norms (unchanged from R6 passing version)
// ---------------------------------------------------------------------------
__global__ __launch_bounds__(256)
void proj_kernel(const float* __restrict__ feat,
                 const float* __restrict__ W,
                 const float* __restrict__ bias,
                 float* __restrict__ nodes_out) {
    __shared__ float Wsm[CC * CC];   // [c][o]
    __shared__ float bsm[CC];
    int tid = threadIdx.x;
    for (int idx = tid; idx < CC * CC; idx += blockDim.x) {
        int o = idx & 63, c = idx >> 6;
        Wsm[c * CC + o] = W[o * CC + c];
    }
    if (tid < CC) bsm[tid] = bias[tid];
    __syncthreads();

    int ng = blockIdx.x * blockDim.x + tid;
    int b = ng >> 12, n = ng & (NN - 1);
    const float* f = feat + (size_t)b * CC * NN + n;

    float acc[CC];
#pragma unroll
    for (int o = 0; o < CC; o++) acc[o] = bsm[o];
    for (int c = 0; c < CC; c++) {
        float fv = f[(size_t)c * NN];
#pragma unroll
        for (int o = 0; o < CC; o++) acc[o] = fmaf(fv, Wsm[c * CC + o], acc[o]);
    }
    float xx = 0.f;
#pragma unroll
    for (int o = 0; o < CC; o++) xx = fmaf(acc[o], acc[o], xx);
    g_xx[ng] = xx;

    float4* dst = (float4*)(nodes_out + (size_t)ng * CC);
#pragma unroll
    for (int o = 0; o < CC / 4; o++)
        dst[o] = make_float4(acc[4 * o], acc[4 * o + 1], acc[4 * o + 2], acc[4 * o + 3]);
}

// ---------------------------------------------------------------------------
// Kernel B: distance tiles via packed f32x2 FMA + fused top-8 (self excluded)
// ---------------------------------------------------------------------------
__global__ __launch_bounds__(THREADS)
void knn_kernel(const float* __restrict__ nodes, float* __restrict__ edges) {
    extern __shared__ float sm[];
    float* XiT2 = sm;                    // [c][2*64] duplicated pairs, stride PADI
    float* XjT  = XiT2 + F_XI2;          // [c][64], stride PADJ; aliased as dt
    float* xxi2 = XjT + F_XJ;            // 128 floats, duplicated pairs
    float* xxj  = xxi2 + 128;            // 64 floats
    float* dt   = XjT;                   // distance tile alias (disjoint lifetime)

    int tid = threadIdx.x;
    int b   = blockIdx.y;
    int i0  = blockIdx.x * TI;
    const float* nodesB = nodes + (size_t)b * NN * CC;

    // Xi tile, duplicated: XiT2[c*PADI + 2r (+1)] = Xi[r][c]
    for (int idx = tid; idx < TI * CC; idx += THREADS) {
        int c = idx & 63, r = idx >> 6;                 // c fastest: coalesced gmem
        float v = nodesB[(size_t)(i0 + r) * CC + c];
        XiT2[c * PADI + 2 * r]     = v;
        XiT2[c * PADI + 2 * r + 1] = v;
    }
    if (tid < TI) {
        float v = g_xx[b * NN + i0 + tid];
        xxi2[2 * tid] = v; xxi2[2 * tid + 1] = v;
    }

    int ty = tid >> 4, tx = tid & 15;    // 16x16 compute mapping, 4x4 micro-tile
    int srow = tid >> 2, spart = tid & 3;
    int iglob = i0 + srow;

    const unsigned long long NEG2 = 0xC0000000C0000000ull;  // (-2.f, -2.f)

    unsigned long long heap[KOUT];
#pragma unroll
    for (int q = 0; q < KOUT; q++) heap[q] = 0xFFFFFFFFFFFFFFFFull;

    __syncthreads();

    for (int jt = 0; jt < NN / TJ; jt++) {
        // Xj tile (transposed, stride PADJ) + xxj
        for (int idx = tid; idx < TJ * CC; idx += THREADS) {
            int r = idx >> 6, c = idx & 63;
            XjT[c * PADJ + r] = nodesB[(size_t)(jt * TJ + r) * CC + c];
        }
        if (tid < TJ) xxj[tid] = g_xx[b * NN + jt * TJ + tid];
        __syncthreads();

        // packed 4x4 micro-tile: 3x LDS.128 + 8x FFMA2 per c
        unsigned long long acc[4][2];
#pragma unroll
        for (int a = 0; a < 4; a++) { acc[a][0] = 0ull; acc[a][1] = 0ull; }

#pragma unroll 4
        for (int c = 0; c < CC; c++) {
            const float* Ar = &XiT2[c * PADI + 8 * ty];
            ulonglong2 a01 = *(const ulonglong2*)Ar;         // (v0,v0),(v1,v1)
            ulonglong2 a23 = *(const ulonglong2*)(Ar + 4);   // (v2,v2),(v3,v3)
            ulonglong2 bp  = *(const ulonglong2*)&XjT[c * PADJ + 4 * tx];
            ffma2(acc[0][0], a01.x, bp.x); ffma2(acc[0][1], a01.x, bp.y);
            ffma2(acc[1][0], a01.y, bp.x); ffma2(acc[1][1], a01.y, bp.y);
            ffma2(acc[2][0], a23.x, bp.x); ffma2(acc[2][1], a23.x, bp.y);
            ffma2(acc[3][0], a23.y, bp.x); ffma2(acc[3][1], a23.y, bp.y);
        }

        __syncthreads();   // XjT reads done; safe to overwrite aliased dt

        // distances -> dt (packed): d = (xi + xxj) + (-2)*dot
        {
            ulonglong2 xjp = *(const ulonglong2*)&xxj[4 * tx];
            ulonglong2 x01 = *(const ulonglong2*)&xxi2[8 * ty];
            ulonglong2 x23 = *(const ulonglong2*)&xxi2[8 * ty + 4];
            unsigned long long xia[4] = {x01.x, x01.y, x23.x, x23.y};
#pragma unroll
            for (int a = 0; a < 4; a++) {
                unsigned long long d0 =
                    fma2v(NEG2, acc[a][0], add2v(xia[a], xjp.x));
                unsigned long long d1 =
                    fma2v(NEG2, acc[a][1], add2v(xia[a], xjp.y));
                ulonglong2 dv; dv.x = d0; dv.y = d1;
                *(ulonglong2*)&dt[(4 * ty + a) * PADJ + 4 * tx] = dv;
            }
        }
        __syncthreads();

        // scan: 4 scanners/row, 16 strided candidates each; skip self
        int jbase = jt * TJ;
#pragma unroll
        for (int s = 0; s < 16; s++) {
            int jl = spart + 4 * s;
            float d = dt[srow * PADJ + jl];
            int j = jbase + jl;
            unsigned long long key =
                ((unsigned long long)__float_as_uint(d) << 32) | (unsigned int)j;
            if (j == iglob) key = 0xFFFFFFFFFFFFFFFFull;
            if (key < heap[KOUT - 1]) {
                heap[KOUT - 1] = key;
#pragma unroll
                for (int q = KOUT - 1; q > 0; q--)
                    if (heap[q] < heap[q - 1]) {
                        unsigned long long t = heap[q];
                        heap[q] = heap[q - 1]; heap[q - 1] = t;
                    }
            }
        }
        __syncthreads();
    }

    // merge the 4 scanner lanes per row (branch-free shfl min), emit top-8
    float* esrc = edges + (size_t)b * EDGE_PER_B;
    float* eidx = esrc + NN * KOUT;
    unsigned long long prev = 0;

#pragma unroll
    for (int r = 0; r < KOUT; r++) {
        unsigned long long cand = 0xFFFFFFFFFFFFFFFFull;
#pragma unroll
        for (int q = 0; q < KOUT; q++) {
            unsigned long long h = heap[q];
            if (h > prev && h < cand) cand = h;
        }
        unsigned long long m = cand;
        unsigned long long o1 = __shfl_xor_sync(0xFFFFFFFFu, m, 1, 4);
        if (o1 < m) m = o1;
        unsigned long long o2 = __shfl_xor_sync(0xFFFFFFFFu, m, 2, 4);
        if (o2 < m) m = o2;
        prev = m;
        if (spart == 0) {
            int nb = (int)(m & 0xFFFFFFFFull);
            esrc[(size_t)iglob * KOUT + r] = (float)iglob;
            eidx[(size_t)iglob * KOUT + r] = (float)nb;
        }
    }
}

// ---------------------------------------------------------------------------
// Launch
// ---------------------------------------------------------------------------
extern "C" void kernel_launch(void* const* d_in, const int* in_sizes, int n_in,
                              void* d_out, int out_size) {
    const float* feat = (const float*)d_in[0];   // features (8,64,64,64)
    const float* W    = (const float*)d_in[1];   // proj_w (64,64)
    const float* bias = (const float*)d_in[2];   // proj_b (64,)
    float* out = (float*)d_out;

    proj_kernel<<<(BATCH * NN) / 256, 256>>>(feat, W, bias, out);

    cudaFuncSetAttribute(knn_kernel, cudaFuncAttributeMaxDynamicSharedMemorySize,
                         SMEM_BYTES);
    dim3 grid(NN / TI, BATCH);
    knn_kernel<<<grid, THREADS, SMEM_BYTES>>>(out, out + NODES_ELEMS);
}

// round 14
// speedup vs baseline: 1.2875x; 1.2875x over previous
#include <cuda_runtime.h>
#include <cstdint>

// Problem constants
#define BATCH 8
#define NN    4096
#define CC    64
#define KOUT  8            // neighbors kept (self excluded explicitly at insert)
#define TI 128
#define TJ 128
#define NJT (NN / TJ)      // 32
#define STR 132            // row stride (floats), 16B-aligned rows
#define THREADS 256

#define NODES_ELEMS (BATCH * NN * CC)
#define EDGE_PER_B  (2 * NN * KOUT)

// smem layout (floats): A[64][STR] | B/dt union (dt = 128*STR) | xxi[128] | xxj[128]
#define F_A   0
#define F_B   (CC * STR)                 // 8448
#define F_XXI (F_B + TI * STR)           // 8448 + 16896 = 25344
#define F_XXJ (F_XXI + TI)
#define SMEM_FLOATS (F_XXJ + TJ)         // 25600
#define SMEM_BYTES  (SMEM_FLOATS * 4)    // 102400 B

__device__ float g_xx[BATCH * NN];

// ---- f32x2 packed helpers (base sm_100-family PTX, not 'a'-gated) ----
__device__ __forceinline__ void ffma2(unsigned long long& d,
                                      unsigned long long a, unsigned long long b) {
    asm("fma.rn.f32x2 %0, %1, %2, %0;" : "+l"(d) : "l"(a), "l"(b));
}
__device__ __forceinline__ unsigned long long fma2v(unsigned long long a,
                                                    unsigned long long b,
                                                    unsigned long long c) {
    unsigned long long d;
    asm("fma.rn.f32x2 %0, %1, %2, %3;" : "=l"(d) : "l"(a), "l"(b), "l"(c));
    return d;
}
__device__ __forceinline__ unsigned long long add2v(unsigned long long a,
                                                    unsigned long long b) {
    unsigned long long d;
    asm("add.rn.f32x2 %0, %1, %2;" : "=l"(d) : "l"(a), "l"(b));
    return d;
}
__device__ __forceinline__ unsigned long long dup2(float f) {
    unsigned long long d;
    asm("mov.b64 %0, {%1, %1};" : "=l"(d) : "f"(f));
    return d;
}

// ---------------------------------------------------------------------------
// Kernel A: projection + squared norms
// ---------------------------------------------------------------------------
__global__ __launch_bounds__(256)
void proj_kernel(const float* __restrict__ feat,
                 const float* __restrict__ W,
                 const float* __restrict__ bias,
                 float* __restrict__ nodes_out) {
    __shared__ float Wsm[CC * CC];   // [c][o]
    __shared__ float bsm[CC];
    int tid = threadIdx.x;
    for (int idx = tid; idx < CC * CC; idx += blockDim.x) {
        int o = idx & 63, c = idx >> 6;
        Wsm[c * CC + o] = W[o * CC + c];
    }
    if (tid < CC) bsm[tid] = bias[tid];
    __syncthreads();

    int ng = blockIdx.x * blockDim.x + tid;
    int b = ng >> 12, n = ng & (NN - 1);
    const float* f = feat + (size_t)b * CC * NN + n;

    float acc[CC];
#pragma unroll
    for (int o = 0; o < CC; o++) acc[o] = bsm[o];
    for (int c = 0; c < CC; c++) {
        float fv = f[(size_t)c * NN];
#pragma unroll
        for (int o = 0; o < CC; o++) acc[o] = fmaf(fv, Wsm[c * CC + o], acc[o]);
    }
    float xx = 0.f;
#pragma unroll
    for (int o = 0; o < CC; o++) xx = fmaf(acc[o], acc[o], xx);
    g_xx[ng] = xx;

    float4* dst = (float4*)(nodes_out + (size_t)ng * CC);
#pragma unroll
    for (int o = 0; o < CC / 4; o++)
        dst[o] = make_float4(acc[4 * o], acc[4 * o + 1], acc[4 * o + 2], acc[4 * o + 3]);
}

// ---------------------------------------------------------------------------
// Kernel B: 128x128 tile, 8x8 register micro-tiles via FFMA2, fused top-8
// ---------------------------------------------------------------------------
__global__ __launch_bounds__(THREADS, 2)
void knn_kernel(const float* __restrict__ nodes, float* __restrict__ edges) {
    extern __shared__ float sm[];
    float* Asm = sm + F_A;            // [c][128], stride STR (persistent)
    float* Bsm = sm + F_B;            // [c][128], stride STR
    float* dt  = sm + F_B;            // [128][STR] distance tile, aliases B
    float* xxi = sm + F_XXI;
    float* xxj = sm + F_XXJ;

    int tid = threadIdx.x;
    int b   = blockIdx.y;
    int i0  = blockIdx.x * TI;
    const float* nodesB = nodes + (size_t)b * NN * CC;

    // A tile transposed: Asm[c*STR + r] = Xi[r][c]
    for (int idx = tid; idx < TI * CC; idx += THREADS) {
        int r = idx >> 6, c = idx & 63;
        Asm[c * STR + r] = nodesB[(size_t)(i0 + r) * CC + c];
    }
    if (tid < TI) xxi[tid] = g_xx[b * NN + i0 + tid];

    int ty = tid >> 4, tx = tid & 15;        // 16x16 threads, 8x8 micro-tile
    int srow = tid >> 1, spart = tid & 1;    // scan: 2 scanners per row
    int iglob = i0 + srow;

    const unsigned long long NEG2 = 0xC0000000C0000000ull;  // (-2.f, -2.f)

    unsigned long long heap[KOUT];
#pragma unroll
    for (int q = 0; q < KOUT; q++) heap[q] = 0xFFFFFFFFFFFFFFFFull;

    __syncthreads();

    for (int jt = 0; jt < NJT; jt++) {
        int j0 = jt * TJ;
        // B tile transposed
        for (int idx = tid; idx < TJ * CC; idx += THREADS) {
            int r = idx >> 6, c = idx & 63;
            Bsm[c * STR + r] = nodesB[(size_t)(j0 + r) * CC + c];
        }
        if (tid < TJ) xxj[tid] = g_xx[b * NN + j0 + tid];
        __syncthreads();

        // 8x8 micro-tile: acc[i][jp] (jp = packed j-pair)
        unsigned long long acc[8][4];
#pragma unroll
        for (int i = 0; i < 8; i++)
#pragma unroll
            for (int p = 0; p < 4; p++) acc[i][p] = 0ull;

#pragma unroll 2
        for (int c = 0; c < CC; c++) {
            const float* Ar = &Asm[c * STR + 8 * ty];
            float4 a0 = *(const float4*)Ar;
            float4 a1 = *(const float4*)(Ar + 4);
            ulonglong2 b01 = *(const ulonglong2*)&Bsm[c * STR + 8 * tx];
            ulonglong2 b23 = *(const ulonglong2*)&Bsm[c * STR + 8 * tx + 4];
            unsigned long long Ad[8];
            Ad[0] = dup2(a0.x); Ad[1] = dup2(a0.y);
            Ad[2] = dup2(a0.z); Ad[3] = dup2(a0.w);
            Ad[4] = dup2(a1.x); Ad[5] = dup2(a1.y);
            Ad[6] = dup2(a1.z); Ad[7] = dup2(a1.w);
#pragma unroll
            for (int i = 0; i < 8; i++) {
                ffma2(acc[i][0], Ad[i], b01.x);
                ffma2(acc[i][1], Ad[i], b01.y);
                ffma2(acc[i][2], Ad[i], b23.x);
                ffma2(acc[i][3], Ad[i], b23.y);
            }
        }

        __syncthreads();   // all Bsm reads done; safe to overwrite aliased dt

        // distances -> dt: d = (-2)*dot + (xi + xxj)
        {
            ulonglong2 xj01 = *(const ulonglong2*)&xxj[8 * tx];
            ulonglong2 xj23 = *(const ulonglong2*)&xxj[8 * tx + 4];
            unsigned long long xjp[4] = {xj01.x, xj01.y, xj23.x, xj23.y};
#pragma unroll
            for (int i = 0; i < 8; i++) {
                unsigned long long xi2 = dup2(xxi[8 * ty + i]);
                ulonglong2 d01, d23;
                d01.x = fma2v(NEG2, acc[i][0], add2v(xi2, xjp[0]));
                d01.y = fma2v(NEG2, acc[i][1], add2v(xi2, xjp[1]));
                d23.x = fma2v(NEG2, acc[i][2], add2v(xi2, xjp[2]));
                d23.y = fma2v(NEG2, acc[i][3], add2v(xi2, xjp[3]));
                float* drow = &dt[(8 * ty + i) * STR + 8 * tx];
                *(ulonglong2*)drow = d01;
                *(ulonglong2*)(drow + 4) = d23;
            }
        }
        __syncthreads();

        // scan: each scanner owns a contiguous 64-col half of its row
        int cbase = 64 * spart;
        const float* srcrow = &dt[srow * STR + cbase];
        int jb0 = j0 + cbase;
#pragma unroll 4
        for (int s = 0; s < 16; s++) {
            float4 dv = *(const float4*)(srcrow + 4 * s);
            float dd[4] = {dv.x, dv.y, dv.z, dv.w};
#pragma unroll
            for (int u = 0; u < 4; u++) {
                int j = jb0 + 4 * s + u;
                unsigned long long key =
                    ((unsigned long long)__float_as_uint(dd[u]) << 32) | (unsigned int)j;
                if (j == iglob) key = 0xFFFFFFFFFFFFFFFFull;
                if (key < heap[KOUT - 1]) {
                    heap[KOUT - 1] = key;
#pragma unroll
                    for (int q = KOUT - 1; q > 0; q--)
                        if (heap[q] < heap[q - 1]) {
                            unsigned long long t = heap[q];
                            heap[q] = heap[q - 1]; heap[q - 1] = t;
                        }
                }
            }
        }
        __syncthreads();
    }

    // merge the 2 scanner lanes per row (shfl width 2), emit top-8
    float* esrc = edges + (size_t)b * EDGE_PER_B;
    float* eidx = esrc + NN * KOUT;
    unsigned long long prev = 0;

#pragma unroll
    for (int r = 0; r < KOUT; r++) {
        unsigned long long cand = 0xFFFFFFFFFFFFFFFFull;
#pragma unroll
        for (int q = 0; q < KOUT; q++) {
            unsigned long long h = heap[q];
            if (h > prev && h < cand) cand = h;
        }
        unsigned long long m = cand;
        unsigned long long o1 = __shfl_xor_sync(0xFFFFFFFFu, m, 1, 2);
        if (o1 < m) m = o1;
        prev = m;
        if (spart == 0) {
            int nb = (int)(m & 0xFFFFFFFFull);
            esrc[(size_t)iglob * KOUT + r] = (float)iglob;
            eidx[(size_t)iglob * KOUT + r] = (float)nb;
        }
    }
}

// ---------------------------------------------------------------------------
// Launch
// ---------------------------------------------------------------------------
extern "C" void kernel_launch(void* const* d_in, const int* in_sizes, int n_in,
                              void* d_out, int out_size) {
    const float* feat = (const float*)d_in[0];   // features (8,64,64,64)
    const float* W    = (const float*)d_in[1];   // proj_w (64,64)
    const float* bias = (const float*)d_in[2];   // proj_b (64,)
    float* out = (float*)d_out;

    proj_kernel<<<(BATCH * NN) / 256, 256>>>(feat, W, bias, out);

    cudaFuncSetAttribute(knn_kernel, cudaFuncAttributeMaxDynamicSharedMemorySize,
                         SMEM_BYTES);
    dim3 grid(NN / TI, BATCH);
    knn_kernel<<<grid, THREADS, SMEM_BYTES>>>(out, out + NODES_ELEMS);
}

// round 15
// speedup vs baseline: 1.3998x; 1.0873x over previous
#include <cuda_runtime.h>
#include <cstdint>

// Problem constants
#define BATCH 8
#define NN    4096
#define CC    64
#define KOUT  8
#define TI 128
#define TJ 128
#define NJT (NN / TJ)      // 32
#define STR 132            // row stride (floats), 16B-aligned rows
#define THREADS 256

#define NODES_ELEMS (BATCH * NN * CC)
#define EDGE_PER_B  (2 * NN * KOUT)

// smem layout (floats): A[64][STR] | B/dt union | xxi[128] | xxj[128]
#define F_A   0
#define F_B   (CC * STR)
#define F_XXI (F_B + TI * STR)
#define F_XXJ (F_XXI + TI)
#define SMEM_FLOATS (F_XXJ + TJ)
#define SMEM_BYTES  (SMEM_FLOATS * 4)   // 102,400 B

__device__ float g_xx[BATCH * NN];

// ---- f32x2 packed helpers ----
__device__ __forceinline__ void ffma2(unsigned long long& d,
                                      unsigned long long a, unsigned long long b) {
    asm("fma.rn.f32x2 %0, %1, %2, %0;" : "+l"(d) : "l"(a), "l"(b));
}
__device__ __forceinline__ unsigned long long dup2(float f) {
    unsigned long long d;
    asm("mov.b64 %0, {%1, %1};" : "=l"(d) : "f"(f));
    return d;
}
__device__ __forceinline__ float2 unpack2(unsigned long long v) {
    float2 r;
    asm("mov.b64 {%0, %1}, %2;" : "=f"(r.x), "=f"(r.y) : "l"(v));
    return r;
}

// ---------------------------------------------------------------------------
// Kernel A: projection + squared norms
// ---------------------------------------------------------------------------
__global__ __launch_bounds__(256)
void proj_kernel(const float* __restrict__ feat,
                 const float* __restrict__ W,
                 const float* __restrict__ bias,
                 float* __restrict__ nodes_out) {
    __shared__ float Wsm[CC * CC];   // [c][o]
    __shared__ float bsm[CC];
    int tid = threadIdx.x;
    for (int idx = tid; idx < CC * CC; idx += blockDim.x) {
        int o = idx & 63, c = idx >> 6;
        Wsm[c * CC + o] = W[o * CC + c];
    }
    if (tid < CC) bsm[tid] = bias[tid];
    __syncthreads();

    int ng = blockIdx.x * blockDim.x + tid;
    int b = ng >> 12, n = ng & (NN - 1);
    const float* f = feat + (size_t)b * CC * NN + n;

    float acc[CC];
#pragma unroll
    for (int o = 0; o < CC; o++) acc[o] = bsm[o];
    for (int c = 0; c < CC; c++) {
        float fv = f[(size_t)c * NN];
#pragma unroll
        for (int o = 0; o < CC; o++) acc[o] = fmaf(fv, Wsm[c * CC + o], acc[o]);
    }
    float xx = 0.f;
#pragma unroll
    for (int o = 0; o < CC; o++) xx = fmaf(acc[o], acc[o], xx);
    g_xx[ng] = xx;

    float4* dst = (float4*)(nodes_out + (size_t)ng * CC);
#pragma unroll
    for (int o = 0; o < CC / 4; o++)
        dst[o] = make_float4(acc[4 * o], acc[4 * o + 1], acc[4 * o + 2], acc[4 * o + 3]);
}

// ---------------------------------------------------------------------------
// Kernel B: 128x128 tiles, 8x8 micro-tiles (split j: 4tx and 64+4tx), FFMA2
// ---------------------------------------------------------------------------
__global__ __launch_bounds__(THREADS, 2)
void knn_kernel(const float* __restrict__ nodes, float* __restrict__ edges) {
    extern __shared__ float sm[];
    float* Asm = sm + F_A;
    float* Bsm = sm + F_B;
    float* dt  = sm + F_B;            // aliases B (disjoint lifetime)
    float* xxi = sm + F_XXI;
    float* xxj = sm + F_XXJ;

    int tid = threadIdx.x;
    int b   = blockIdx.y;
    int i0  = blockIdx.x * TI;
    const float* nodesB = nodes + (size_t)b * NN * CC;

    // A tile transposed (vectorized gmem read)
#pragma unroll
    for (int q = 0; q < 8; q++) {
        int e = q * 256 + tid;                 // 0..2047
        int r = e >> 4;                        // row 0..127
        int c4 = (e & 15) << 2;                // col group
        float4 v = *(const float4*)&nodesB[(size_t)(i0 + r) * CC + c4];
        Asm[(c4 + 0) * STR + r] = v.x;
        Asm[(c4 + 1) * STR + r] = v.y;
        Asm[(c4 + 2) * STR + r] = v.z;
        Asm[(c4 + 3) * STR + r] = v.w;
    }
    if (tid < TI) xxi[tid] = g_xx[b * NN + i0 + tid];

    int ty = tid >> 4, tx = tid & 15;          // 16x16 threads
    int rbase = 8 * ty;                        // 8 rows per thread
    int cb1 = 4 * tx, cb2 = 64 + 4 * tx;       // two conflict-free col groups
    int srow = tid >> 1, spart = tid & 1;      // scan: 2 scanners per row
    int iglob = i0 + srow;
    bool diagB = false;                        // set per tile

    unsigned long long heap[KOUT];
#pragma unroll
    for (int q = 0; q < KOUT; q++) heap[q] = 0xFFFFFFFFFFFFFFFFull;

    __syncthreads();

    for (int jt = 0; jt < NJT; jt++) {
        int j0 = jt * TJ;
        // B tile transposed (vectorized gmem read)
#pragma unroll
        for (int q = 0; q < 8; q++) {
            int e = q * 256 + tid;
            int r = e >> 4;
            int c4 = (e & 15) << 2;
            float4 v = *(const float4*)&nodesB[(size_t)(j0 + r) * CC + c4];
            Bsm[(c4 + 0) * STR + r] = v.x;
            Bsm[(c4 + 1) * STR + r] = v.y;
            Bsm[(c4 + 2) * STR + r] = v.z;
            Bsm[(c4 + 3) * STR + r] = v.w;
        }
        if (tid < TJ) xxj[tid] = g_xx[b * NN + j0 + tid];
        __syncthreads();

        // 8x8 micro-tile: acc[i][p], p = {cb1 pair0, cb1 pair1, cb2 pair0, cb2 pair1}
        unsigned long long acc[8][4];
#pragma unroll
        for (int i = 0; i < 8; i++)
#pragma unroll
            for (int p = 0; p < 4; p++) acc[i][p] = 0ull;

#pragma unroll 2
        for (int c = 0; c < CC; c++) {
            const float* Ar = &Asm[c * STR + rbase];
            float4 a0 = *(const float4*)Ar;
            float4 a1 = *(const float4*)(Ar + 4);
            ulonglong2 b1 = *(const ulonglong2*)&Bsm[c * STR + cb1];  // conflict-free
            ulonglong2 b2 = *(const ulonglong2*)&Bsm[c * STR + cb2];  // conflict-free
            unsigned long long Ad[8];
            Ad[0] = dup2(a0.x); Ad[1] = dup2(a0.y);
            Ad[2] = dup2(a0.z); Ad[3] = dup2(a0.w);
            Ad[4] = dup2(a1.x); Ad[5] = dup2(a1.y);
            Ad[6] = dup2(a1.z); Ad[7] = dup2(a1.w);
#pragma unroll
            for (int i = 0; i < 8; i++) {
                ffma2(acc[i][0], Ad[i], b1.x);
                ffma2(acc[i][1], Ad[i], b1.y);
                ffma2(acc[i][2], Ad[i], b2.x);
                ffma2(acc[i][3], Ad[i], b2.y);
            }
        }

        __syncthreads();   // Bsm reads done; safe to overwrite aliased dt

        // distances -> dt; diagonal self gets +INF so the scan never sees it
        {
            bool diag = (j0 == i0);
            float xj1[4], xj2[4];
#pragma unroll
            for (int u = 0; u < 4; u++) { xj1[u] = xxj[cb1 + u]; xj2[u] = xxj[cb2 + u]; }
#pragma unroll
            for (int i = 0; i < 8; i++) {
                int row = rbase + i;
                float xi2 = xxi[row];
                float2 p0 = unpack2(acc[i][0]);
                float2 p1 = unpack2(acc[i][1]);
                float2 p2 = unpack2(acc[i][2]);
                float2 p3 = unpack2(acc[i][3]);
                float d1[4] = {fmaf(-2.f, p0.x, xi2 + xj1[0]),
                               fmaf(-2.f, p0.y, xi2 + xj1[1]),
                               fmaf(-2.f, p1.x, xi2 + xj1[2]),
                               fmaf(-2.f, p1.y, xi2 + xj1[3])};
                float d2[4] = {fmaf(-2.f, p2.x, xi2 + xj2[0]),
                               fmaf(-2.f, p2.y, xi2 + xj2[1]),
                               fmaf(-2.f, p3.x, xi2 + xj2[2]),
                               fmaf(-2.f, p3.y, xi2 + xj2[3])};
                if (diag) {
                    int u1 = row - cb1;
                    if (u1 >= 0 && u1 < 4) d1[u1] = __int_as_float(0x7f800000);
                    int u2 = row - cb2;
                    if (u2 >= 0 && u2 < 4) d2[u2] = __int_as_float(0x7f800000);
                }
                float* drow = &dt[row * STR];
                *(float4*)(drow + cb1) = make_float4(d1[0], d1[1], d1[2], d1[3]);
                *(float4*)(drow + cb2) = make_float4(d2[0], d2[1], d2[2], d2[3]);
            }
        }
        __syncthreads();

        // scan: 64 contiguous cols per scanner, fmin4 early-out vs heap max
        {
            int cbase = 64 * spart;
            const float* srcrow = &dt[srow * STR + cbase];
            int jb0 = j0 + cbase;
            unsigned int thrbits = (unsigned int)(heap[KOUT - 1] >> 32);
#pragma unroll 4
            for (int s = 0; s < 16; s++) {
                float4 dv = *(const float4*)(srcrow + 4 * s);
                float mn = fminf(fminf(dv.x, dv.y), fminf(dv.z, dv.w));
                if (__float_as_uint(mn) <= thrbits) {
                    float dd[4] = {dv.x, dv.y, dv.z, dv.w};
#pragma unroll
                    for (int u = 0; u < 4; u++) {
                        unsigned long long key =
                            ((unsigned long long)__float_as_uint(dd[u]) << 32) |
                            (unsigned int)(jb0 + 4 * s + u);
                        if (key < heap[KOUT - 1]) {
                            heap[KOUT - 1] = key;
#pragma unroll
                            for (int q = KOUT - 1; q > 0; q--)
                                if (heap[q] < heap[q - 1]) {
                                    unsigned long long t = heap[q];
                                    heap[q] = heap[q - 1]; heap[q - 1] = t;
                                }
                        }
                    }
                    thrbits = (unsigned int)(heap[KOUT - 1] >> 32);
                }
            }
        }
        __syncthreads();
        (void)diagB;
    }

    // merge the 2 scanner lanes per row (shfl width 2), emit top-8
    float* esrc = edges + (size_t)b * EDGE_PER_B;
    float* eidx = esrc + NN * KOUT;
    unsigned long long prev = 0;

#pragma unroll
    for (int r = 0; r < KOUT; r++) {
        unsigned long long cand = 0xFFFFFFFFFFFFFFFFull;
#pragma unroll
        for (int q = 0; q < KOUT; q++) {
            unsigned long long h = heap[q];
            if (h > prev && h < cand) cand = h;
        }
        unsigned long long m = cand;
        unsigned long long o1 = __shfl_xor_sync(0xFFFFFFFFu, m, 1, 2);
        if (o1 < m) m = o1;
        prev = m;
        if (spart == 0) {
            int nb = (int)(m & 0xFFFFFFFFull);
            esrc[(size_t)iglob * KOUT + r] = (float)iglob;
            eidx[(size_t)iglob * KOUT + r] = (float)nb;
        }
    }
}

// ---------------------------------------------------------------------------
// Launch
// ---------------------------------------------------------------------------
extern "C" void kernel_launch(void* const* d_in, const int* in_sizes, int n_in,
                              void* d_out, int out_size) {
    const float* feat = (const float*)d_in[0];   // features (8,64,64,64)
    const float* W    = (const float*)d_in[1];   // proj_w (64,64)
    const float* bias = (const float*)d_in[2];   // proj_b (64,)
    float* out = (float*)d_out;

    proj_kernel<<<(BATCH * NN) / 256, 256>>>(feat, W, bias, out);

    cudaFuncSetAttribute(knn_kernel, cudaFuncAttributeMaxDynamicSharedMemorySize,
                         SMEM_BYTES);
    dim3 grid(NN / TI, BATCH);
    knn_kernel<<<grid, THREADS, SMEM_BYTES>>>(out, out + NODES_ELEMS);
}

// round 16
// speedup vs baseline: 1.4867x; 1.0621x over previous
#include <cuda_runtime.h>
#include <cstdint>

// Problem constants
#define BATCH 8
#define NN    4096
#define CC    64
#define KOUT  8
#define TI 128
#define TJ 128
#define NJT (NN / TJ)      // 32
#define STR 132            // [c][r] tile row stride (floats), 16B-aligned rows
#define THREADS 256

#define NODES_ELEMS (BATCH * NN * CC)
#define EDGE_PER_B  (2 * NN * KOUT)

// smem layout (floats): A[64][STR] | B/dt union | xxi[128] | xxj[128]
#define F_A   0
#define F_B   (CC * STR)
#define F_XXI (F_B + TI * STR)
#define F_XXJ (F_XXI + TI)
#define SMEM_FLOATS (F_XXJ + TJ)
#define SMEM_BYTES  (SMEM_FLOATS * 4)   // 102,400 B

__device__ float g_xx[BATCH * NN];
__device__ float g_nT[(size_t)BATCH * CC * NN];   // transposed nodes [b][c][n]

// ---- f32x2 packed helpers ----
__device__ __forceinline__ void ffma2(unsigned long long& d,
                                      unsigned long long a, unsigned long long b) {
    asm("fma.rn.f32x2 %0, %1, %2, %0;" : "+l"(d) : "l"(a), "l"(b));
}
__device__ __forceinline__ unsigned long long dup2(float f) {
    unsigned long long d;
    asm("mov.b64 %0, {%1, %1};" : "=l"(d) : "f"(f));
    return d;
}
__device__ __forceinline__ float2 unpack2(unsigned long long v) {
    float2 r;
    asm("mov.b64 {%0, %1}, %2;" : "=f"(r.x), "=f"(r.y) : "l"(v));
    return r;
}
// ---- cp.async (LDGSTS) helpers ----
__device__ __forceinline__ uint32_t smem_u32(const void* p) {
    uint32_t a;
    asm("{ .reg .u64 t; cvta.to.shared.u64 t, %1; cvt.u32.u64 %0, t; }" : "=r"(a) : "l"(p));
    return a;
}
__device__ __forceinline__ void cpa16(uint32_t dst, const void* src) {
    asm volatile("cp.async.cg.shared.global [%0], [%1], 16;" :: "r"(dst), "l"(src));
}
__device__ __forceinline__ void cpa_commit() {
    asm volatile("cp.async.commit_group;" ::: "memory");
}
__device__ __forceinline__ void cpa_wait0() {
    asm volatile("cp.async.wait_group 0;" ::: "memory");
}

// ---------------------------------------------------------------------------
// Kernel A: projection + squared norms + transposed copy g_nT[b][c][n]
// ---------------------------------------------------------------------------
__global__ __launch_bounds__(256)
void proj_kernel(const float* __restrict__ feat,
                 const float* __restrict__ W,
                 const float* __restrict__ bias,
                 float* __restrict__ nodes_out) {
    __shared__ float Wsm[CC * CC];   // [c][o]
    __shared__ float bsm[CC];
    int tid = threadIdx.x;
    for (int idx = tid; idx < CC * CC; idx += blockDim.x) {
        int o = idx & 63, c = idx >> 6;
        Wsm[c * CC + o] = W[o * CC + c];
    }
    if (tid < CC) bsm[tid] = bias[tid];
    __syncthreads();

    int ng = blockIdx.x * blockDim.x + tid;
    int b = ng >> 12, n = ng & (NN - 1);
    const float* f = feat + (size_t)b * CC * NN + n;

    float acc[CC];
#pragma unroll
    for (int o = 0; o < CC; o++) acc[o] = bsm[o];
    for (int c = 0; c < CC; c++) {
        float fv = f[(size_t)c * NN];
#pragma unroll
        for (int o = 0; o < CC; o++) acc[o] = fmaf(fv, Wsm[c * CC + o], acc[o]);
    }
    float xx = 0.f;
#pragma unroll
    for (int o = 0; o < CC; o++) xx = fmaf(acc[o], acc[o], xx);
    g_xx[ng] = xx;

    // row-major nodes (output)
    float4* dst = (float4*)(nodes_out + (size_t)ng * CC);
#pragma unroll
    for (int o = 0; o < CC / 4; o++)
        dst[o] = make_float4(acc[4 * o], acc[4 * o + 1], acc[4 * o + 2], acc[4 * o + 3]);

    // transposed copy: lanes vary n -> coalesced per o
    float* nT = g_nT + (size_t)b * CC * NN + n;
#pragma unroll
    for (int o = 0; o < CC; o++) nT[(size_t)o * NN] = acc[o];
}

// ---------------------------------------------------------------------------
// Kernel B: 128x128 tiles, 8x8 micro-tiles FFMA2; tiles loaded via cp.async
// from the pre-transposed g_nT (conflict-free contiguous smem stores)
// ---------------------------------------------------------------------------
__global__ __launch_bounds__(THREADS, 2)
void knn_kernel(float* __restrict__ edges) {
    extern __shared__ float sm[];
    float* Asm = sm + F_A;
    float* Bsm = sm + F_B;
    float* dt  = sm + F_B;            // aliases B (disjoint lifetime)
    float* xxi = sm + F_XXI;
    float* xxj = sm + F_XXJ;
    uint32_t smb = smem_u32(sm);

    int tid = threadIdx.x;
    int b   = blockIdx.y;
    int i0  = blockIdx.x * TI;
    const float* nTb = g_nT + (size_t)b * CC * NN;

    // A tile: direct [c][n] rows from g_nT; warp = one c, contiguous STS
#pragma unroll
    for (int q = 0; q < 8; q++) {
        int e = q * 256 + tid;                 // 0..2047
        int c = e >> 5, r4 = (e & 31) << 2;    // c row, float4 group
        cpa16(smb + (uint32_t)(F_A + c * STR + r4) * 4,
              nTb + (size_t)c * NN + i0 + r4);
    }
    // B tile 0
#pragma unroll
    for (int q = 0; q < 8; q++) {
        int e = q * 256 + tid;
        int c = e >> 5, r4 = (e & 31) << 2;
        cpa16(smb + (uint32_t)(F_B + c * STR + r4) * 4,
              nTb + (size_t)c * NN + 0 + r4);
    }
    cpa_commit();
    if (tid < TI) xxi[tid] = g_xx[b * NN + i0 + tid];
    if (tid < TJ) xxj[tid] = g_xx[b * NN + tid];

    int ty = tid >> 4, tx = tid & 15;          // 16x16 threads
    int rbase = 8 * ty;
    int cb1 = 4 * tx, cb2 = 64 + 4 * tx;
    int srow = tid >> 1, spart = tid & 1;
    int iglob = i0 + srow;

    unsigned long long heap[KOUT];
#pragma unroll
    for (int q = 0; q < KOUT; q++) heap[q] = 0xFFFFFFFFFFFFFFFFull;

    cpa_wait0();
    __syncthreads();

    for (int jt = 0; jt < NJT; jt++) {
        int j0 = jt * TJ;

        // 8x8 micro-tile FMA
        unsigned long long acc[8][4];
#pragma unroll
        for (int i = 0; i < 8; i++)
#pragma unroll
            for (int p = 0; p < 4; p++) acc[i][p] = 0ull;

#pragma unroll 2
        for (int c = 0; c < CC; c++) {
            const float* Ar = &Asm[c * STR + rbase];
            float4 a0 = *(const float4*)Ar;
            float4 a1 = *(const float4*)(Ar + 4);
            ulonglong2 b1 = *(const ulonglong2*)&Bsm[c * STR + cb1];
            ulonglong2 b2 = *(const ulonglong2*)&Bsm[c * STR + cb2];
            unsigned long long Ad[8];
            Ad[0] = dup2(a0.x); Ad[1] = dup2(a0.y);
            Ad[2] = dup2(a0.z); Ad[3] = dup2(a0.w);
            Ad[4] = dup2(a1.x); Ad[5] = dup2(a1.y);
            Ad[6] = dup2(a1.z); Ad[7] = dup2(a1.w);
#pragma unroll
            for (int i = 0; i < 8; i++) {
                ffma2(acc[i][0], Ad[i], b1.x);
                ffma2(acc[i][1], Ad[i], b1.y);
                ffma2(acc[i][2], Ad[i], b2.x);
                ffma2(acc[i][3], Ad[i], b2.y);
            }
        }

        __syncthreads();   // Bsm reads done; safe to overwrite aliased dt

        // distances -> dt; self on diagonal tile patched to +INF
        {
            bool diag = (j0 == i0);
            float xj1[4], xj2[4];
#pragma unroll
            for (int u = 0; u < 4; u++) { xj1[u] = xxj[cb1 + u]; xj2[u] = xxj[cb2 + u]; }
#pragma unroll
            for (int i = 0; i < 8; i++) {
                int row = rbase + i;
                float xi2 = xxi[row];
                float2 p0 = unpack2(acc[i][0]);
                float2 p1 = unpack2(acc[i][1]);
                float2 p2 = unpack2(acc[i][2]);
                float2 p3 = unpack2(acc[i][3]);
                float d1[4] = {fmaf(-2.f, p0.x, xi2 + xj1[0]),
                               fmaf(-2.f, p0.y, xi2 + xj1[1]),
                               fmaf(-2.f, p1.x, xi2 + xj1[2]),
                               fmaf(-2.f, p1.y, xi2 + xj1[3])};
                float d2[4] = {fmaf(-2.f, p2.x, xi2 + xj2[0]),
                               fmaf(-2.f, p2.y, xi2 + xj2[1]),
                               fmaf(-2.f, p3.x, xi2 + xj2[2]),
                               fmaf(-2.f, p3.y, xi2 + xj2[3])};
                if (diag) {
                    int u1 = row - cb1;
                    if (u1 >= 0 && u1 < 4) d1[u1] = __int_as_float(0x7f800000);
                    int u2 = row - cb2;
                    if (u2 >= 0 && u2 < 4) d2[u2] = __int_as_float(0x7f800000);
                }
                float* drow = &dt[row * STR];
                *(float4*)(drow + cb1) = make_float4(d1[0], d1[1], d1[2], d1[3]);
                *(float4*)(drow + cb2) = make_float4(d2[0], d2[1], d2[2], d2[3]);
            }
        }
        __syncthreads();

        // scan: 64 contiguous cols per scanner, fmin4 early-out vs heap max
        {
            int cbase = 64 * spart;
            const float* srcrow = &dt[srow * STR + cbase];
            int jb0 = j0 + cbase;
            unsigned int thrbits = (unsigned int)(heap[KOUT - 1] >> 32);
#pragma unroll 4
            for (int s = 0; s < 16; s++) {
                float4 dv = *(const float4*)(srcrow + 4 * s);
                float mn = fminf(fminf(dv.x, dv.y), fminf(dv.z, dv.w));
                if (__float_as_uint(mn) <= thrbits) {
                    float dd[4] = {dv.x, dv.y, dv.z, dv.w};
#pragma unroll
                    for (int u = 0; u < 4; u++) {
                        unsigned long long key =
                            ((unsigned long long)__float_as_uint(dd[u]) << 32) |
                            (unsigned int)(jb0 + 4 * s + u);
                        if (key < heap[KOUT - 1]) {
                            heap[KOUT - 1] = key;
#pragma unroll
                            for (int q = KOUT - 1; q > 0; q--)
                                if (heap[q] < heap[q - 1]) {
                                    unsigned long long t = heap[q];
                                    heap[q] = heap[q - 1]; heap[q - 1] = t;
                                }
                        }
                    }
                    thrbits = (unsigned int)(heap[KOUT - 1] >> 32);
                }
            }
        }
        __syncthreads();   // scan done before next B tile overwrites dt/B

        // next B tile via cp.async (conflict-free contiguous stores)
        if (jt + 1 < NJT) {
            int jn = (jt + 1) * TJ;
#pragma unroll
            for (int q = 0; q < 8; q++) {
                int e = q * 256 + tid;
                int c = e >> 5, r4 = (e & 31) << 2;
                cpa16(smb + (uint32_t)(F_B + c * STR + r4) * 4,
                      nTb + (size_t)c * NN + jn + r4);
            }
            cpa_commit();
            if (tid < TJ) xxj[tid] = g_xx[b * NN + jn + tid];
            cpa_wait0();
            __syncthreads();
        }
    }

    // merge the 2 scanner lanes per row (shfl width 2), emit top-8
    float* esrc = edges + (size_t)b * EDGE_PER_B;
    float* eidx = esrc + NN * KOUT;
    unsigned long long prev = 0;

#pragma unroll
    for (int r = 0; r < KOUT; r++) {
        unsigned long long cand = 0xFFFFFFFFFFFFFFFFull;
#pragma unroll
        for (int q = 0; q < KOUT; q++) {
            unsigned long long h = heap[q];
            if (h > prev && h < cand) cand = h;
        }
        unsigned long long m = cand;
        unsigned long long o1 = __shfl_xor_sync(0xFFFFFFFFu, m, 1, 2);
        if (o1 < m) m = o1;
        prev = m;
        if (spart == 0) {
            int nb = (int)(m & 0xFFFFFFFFull);
            esrc[(size_t)iglob * KOUT + r] = (float)iglob;
            eidx[(size_t)iglob * KOUT + r] = (float)nb;
        }
    }
}

// ---------------------------------------------------------------------------
// Launch
// ---------------------------------------------------------------------------
extern "C" void kernel_launch(void* const* d_in, const int* in_sizes, int n_in,
                              void* d_out, int out_size) {
    const float* feat = (const float*)d_in[0];   // features (8,64,64,64)
    const float* W    = (const float*)d_in[1];   // proj_w (64,64)
    const float* bias = (const float*)d_in[2];   // proj_b (64,)
    float* out = (float*)d_out;

    proj_kernel<<<(BATCH * NN) / 256, 256>>>(feat, W, bias, out);

    cudaFuncSetAttribute(knn_kernel, cudaFuncAttributeMaxDynamicSharedMemorySize,
                         SMEM_BYTES);
    dim3 grid(NN / TI, BATCH);
    knn_kernel<<<grid, THREADS, SMEM_BYTES>>>(out + NODES_ELEMS);
}